// round 2
// baseline (speedup 1.0000x reference)
#include <cuda_runtime.h>
#include <cuda_bf16.h>
#include <cstdint>

#define N_B    131072
#define D_IN   128
#define D_OUT  512
#define VBS    128
#define EPS_BN 1e-5f

// ---------------- SMEM layout (bytes), kernel 1 ----------------
// 128x128 bf16 tile, 256B row stride (16 x 16B chunks), XOR-swizzled
#define SA_HI   0
#define SA_LO   32768
#define SW_HI   65536
#define SW_LO   98304
#define SSUM    131072      // 4 warpsM x 128 cols f32
#define SSQ     133120
#define SAB_A   135168      // 128 f32
#define SAB_B   135680      // 128 f32
#define SM_TOT  136192

__device__ __forceinline__ uint32_t smem_u32(const void* p) {
    uint32_t a;
    asm("{ .reg .u64 t; cvta.to.shared.u64 t, %1; cvt.u32.u64 %0, t; }" : "=r"(a) : "l"(p));
    return a;
}
__device__ __forceinline__ void ldsm4(uint32_t* r, uint32_t addr) {
    asm volatile("ldmatrix.sync.aligned.m8n8.x4.shared.b16 {%0,%1,%2,%3}, [%4];"
                 : "=r"(r[0]), "=r"(r[1]), "=r"(r[2]), "=r"(r[3]) : "r"(addr));
}
__device__ __forceinline__ void mma16816(float* c, const uint32_t* a, const uint32_t* b) {
    asm volatile("mma.sync.aligned.m16n8k16.row.col.f32.bf16.bf16.f32 "
                 "{%0,%1,%2,%3}, {%4,%5,%6,%7}, {%8,%9}, {%0,%1,%2,%3};"
                 : "+f"(c[0]), "+f"(c[1]), "+f"(c[2]), "+f"(c[3])
                 : "r"(a[0]), "r"(a[1]), "r"(a[2]), "r"(a[3]), "r"(b[0]), "r"(b[1]));
}
__device__ __forceinline__ uint32_t pkbf(float a, float b) {
    __nv_bfloat162 t = __floats2bfloat162_rn(a, b);
    union { __nv_bfloat162 v; uint32_t u; } cv; cv.v = t;
    return cv.u;
}

// load a 128x128 f32 tile (row-major, stride 128) -> split bf16 hi/lo, swizzled smem
__device__ __forceinline__ void load_split_tile(const float* __restrict__ g,
                                                char* sm_hi, char* sm_lo, int tid) {
    #pragma unroll
    for (int i = 0; i < 4; i++) {
        int idx = tid + i * 512;                 // 2048 chunk-slots total
        int row = idx >> 4, ch = idx & 15;
        const float4* gp = reinterpret_cast<const float4*>(g + row * 128 + ch * 8);
        float4 u = gp[0], v = gp[1];
        float h0 = __bfloat162float(__float2bfloat16_rn(u.x));
        float h1 = __bfloat162float(__float2bfloat16_rn(u.y));
        float h2 = __bfloat162float(__float2bfloat16_rn(u.z));
        float h3 = __bfloat162float(__float2bfloat16_rn(u.w));
        float h4 = __bfloat162float(__float2bfloat16_rn(v.x));
        float h5 = __bfloat162float(__float2bfloat16_rn(v.y));
        float h6 = __bfloat162float(__float2bfloat16_rn(v.z));
        float h7 = __bfloat162float(__float2bfloat16_rn(v.w));
        uint4 hi4 = make_uint4(pkbf(h0, h1), pkbf(h2, h3), pkbf(h4, h5), pkbf(h6, h7));
        uint4 lo4 = make_uint4(pkbf(u.x - h0, u.y - h1), pkbf(u.z - h2, u.w - h3),
                               pkbf(v.x - h4, v.y - h5), pkbf(v.z - h6, v.w - h7));
        uint32_t off = (uint32_t)(row * 256 + ((ch ^ (row & 7)) << 4));
        *reinterpret_cast<uint4*>(sm_hi + off) = hi4;
        *reinterpret_cast<uint4*>(sm_lo + off) = lo4;
    }
}

// ============================================================================
// Kernel 1: split-bf16 mma.sync GEMM + GhostBN + priors -> y written to out
// grid = 1024 (one CTA per virtual batch), block = 512
// ============================================================================
__global__ __launch_bounds__(512, 1) void fused_gemm_gbn(
    float* __restrict__ out, const float* __restrict__ priors,
    const float* __restrict__ feat, const float* __restrict__ W,
    const float* __restrict__ gamma, const float* __restrict__ beta)
{
    extern __shared__ char smem[];
    const uint32_t sb = smem_u32(smem);
    const int tid = threadIdx.x;
    const int w = tid >> 5, lane = tid & 31;
    const int mw = w & 3, nw = w >> 2;           // warp grid 4(M) x 4(N)
    const int m0 = blockIdx.x * VBS;

    float* ssum = reinterpret_cast<float*>(smem + SSUM);
    float* ssq  = reinterpret_cast<float*>(smem + SSQ);
    float* aarr = reinterpret_cast<float*>(smem + SAB_A);
    float* barr = reinterpret_cast<float*>(smem + SAB_B);

    // ---- A tile (feat 128x128) once ----
    load_split_tile(feat + (size_t)m0 * D_IN, smem + SA_HI, smem + SA_LO, tid);

    // per-lane ldmatrix address components (rows constant across k-steps)
    const int a_row = mw * 32 + (((lane >> 3) & 1) << 3) + (lane & 7);
    const int a_sel = lane >> 4;                   // +chunk
    const int b_row = nw * 32 + ((lane >> 4) << 3) + (lane & 7);
    const int b_sel = (lane >> 3) & 1;
    const int a_m7 = a_row & 7, b_m7 = b_row & 7;

    #pragma unroll 1
    for (int chunk = 0; chunk < 4; chunk++) {
        // ---- W chunk (128 n-rows x 128 k) ----
        load_split_tile(W + (size_t)chunk * 128 * D_IN, smem + SW_HI, smem + SW_LO, tid);
        __syncthreads();

        // ---- GEMM: acc[mt][nt][4], warp tile 32x32 ----
        float acc[2][4][4];
        #pragma unroll
        for (int mt = 0; mt < 2; mt++)
            #pragma unroll
            for (int nt = 0; nt < 4; nt++)
                #pragma unroll
                for (int q = 0; q < 4; q++) acc[mt][nt][q] = 0.0f;

        #pragma unroll
        for (int s = 0; s < 8; s++) {
            uint32_t aH[2][4], aL[2][4], bH[2][4], bL[2][4];
            #pragma unroll
            for (int mt = 0; mt < 2; mt++) {
                uint32_t off = (uint32_t)((a_row + mt * 16) * 256 +
                               (((2 * s + a_sel) ^ a_m7) << 4));
                ldsm4(aH[mt], sb + SA_HI + off);
                ldsm4(aL[mt], sb + SA_LO + off);
            }
            #pragma unroll
            for (int np = 0; np < 2; np++) {
                uint32_t off = (uint32_t)((b_row + np * 16) * 256 +
                               (((2 * s + b_sel) ^ b_m7) << 4));
                ldsm4(bH[np], sb + SW_HI + off);
                ldsm4(bL[np], sb + SW_LO + off);
            }
            #pragma unroll
            for (int mt = 0; mt < 2; mt++)
                #pragma unroll
                for (int nt = 0; nt < 4; nt++) {
                    const uint32_t* bh = &bH[nt >> 1][(nt & 1) * 2];
                    const uint32_t* bl = &bL[nt >> 1][(nt & 1) * 2];
                    mma16816(acc[mt][nt], aH[mt], bh);   // hi*hi
                    mma16816(acc[mt][nt], aH[mt], bl);   // hi*lo
                    mma16816(acc[mt][nt], aL[mt], bh);   // lo*hi
                }
        }

        // ---- column stats: sum/sumsq over this warp's 32 rows ----
        #pragma unroll
        for (int nt = 0; nt < 4; nt++) {
            float s0 = 0.f, s1 = 0.f, q0 = 0.f, q1 = 0.f;
            #pragma unroll
            for (int mt = 0; mt < 2; mt++) {
                float c0 = acc[mt][nt][0], c1 = acc[mt][nt][1];
                float c2 = acc[mt][nt][2], c3 = acc[mt][nt][3];
                s0 += c0 + c2;  s1 += c1 + c3;
                q0 += c0 * c0 + c2 * c2;  q1 += c1 * c1 + c3 * c3;
            }
            #pragma unroll
            for (int o = 4; o < 32; o <<= 1) {
                s0 += __shfl_xor_sync(0xffffffffu, s0, o);
                s1 += __shfl_xor_sync(0xffffffffu, s1, o);
                q0 += __shfl_xor_sync(0xffffffffu, q0, o);
                q1 += __shfl_xor_sync(0xffffffffu, q1, o);
            }
            if (lane < 4) {
                int col = nw * 32 + nt * 8 + 2 * lane;
                ssum[mw * 128 + col]     = s0;  ssum[mw * 128 + col + 1] = s1;
                ssq [mw * 128 + col]     = q0;  ssq [mw * 128 + col + 1] = q1;
            }
        }
        __syncthreads();

        // ---- fold BN into per-col affine (deterministic combine) ----
        if (tid < 128) {
            int c = tid;
            float s = ssum[c] + ssum[128 + c] + ssum[256 + c] + ssum[384 + c];
            float q = ssq[c]  + ssq[128 + c]  + ssq[256 + c]  + ssq[384 + c];
            float mean = s * (1.0f / VBS);
            float var  = q * (1.0f / VBS) - mean * mean;
            float av = gamma[chunk * 128 + c] * rsqrtf(var + EPS_BN);
            aarr[c] = av;
            barr[c] = beta[chunk * 128 + c] - mean * av;
        }
        __syncthreads();

        // ---- apply + multiply priors + store y ----
        #pragma unroll
        for (int nt = 0; nt < 4; nt++) {
            int col = nw * 32 + nt * 8 + 2 * (lane & 3);
            int gcol = chunk * 128 + col;
            float a0 = aarr[col],     b0 = barr[col];
            float a1 = aarr[col + 1], b1 = barr[col + 1];
            #pragma unroll
            for (int mt = 0; mt < 2; mt++) {
                int r0 = m0 + mw * 32 + mt * 16 + (lane >> 2);
                int r1 = r0 + 8;
                float2 p0 = *reinterpret_cast<const float2*>(priors + (size_t)r0 * D_OUT + gcol);
                float2 p1 = *reinterpret_cast<const float2*>(priors + (size_t)r1 * D_OUT + gcol);
                float2 y0, y1;
                y0.x = fmaf(acc[mt][nt][0], a0, b0) * p0.x;
                y0.y = fmaf(acc[mt][nt][1], a1, b1) * p0.y;
                y1.x = fmaf(acc[mt][nt][2], a0, b0) * p1.x;
                y1.y = fmaf(acc[mt][nt][3], a1, b1) * p1.y;
                *reinterpret_cast<float2*>(out + (size_t)r0 * D_OUT + gcol) = y0;
                *reinterpret_cast<float2*>(out + (size_t)r1 * D_OUT + gcol) = y1;
            }
        }
        // next loop iteration's load_split_tile is fenced by its __syncthreads
    }
}

// ============================================================================
// Kernel 2: sparsemax in-place, one warp per row (512 = 16 f32 regs/lane).
// Monotone Newton on f(t)=sum relu(y-t)-1 from t0=max-1 (guaranteed bracket);
// exact fixed point of the piecewise-linear equation, no sort needed.
// ============================================================================
__global__ __launch_bounds__(256) void sparsemax_k(float* __restrict__ out)
{
    const int gw = (int)((blockIdx.x * 256u + threadIdx.x) >> 5);   // row
    const int lane = threadIdx.x & 31;
    float4* rp = reinterpret_cast<float4*>(out + (size_t)gw * D_OUT);

    float4 v[4];
    #pragma unroll
    for (int j = 0; j < 4; j++) v[j] = rp[j * 32 + lane];

    float m = v[0].x;
    #pragma unroll
    for (int j = 0; j < 4; j++) {
        m = fmaxf(m, v[j].x); m = fmaxf(m, v[j].y);
        m = fmaxf(m, v[j].z); m = fmaxf(m, v[j].w);
    }
    #pragma unroll
    for (int o = 16; o; o >>= 1) m = fmaxf(m, __shfl_xor_sync(0xffffffffu, m, o));

    float tau = m - 1.0f;
    #pragma unroll 1
    for (int it = 0; it < 64; it++) {
        float s = 0.0f, c = 0.0f;
        #pragma unroll
        for (int j = 0; j < 4; j++) {
            float d;
            d = v[j].x - tau; if (d > 0.0f) { s += d; c += 1.0f; }
            d = v[j].y - tau; if (d > 0.0f) { s += d; c += 1.0f; }
            d = v[j].z - tau; if (d > 0.0f) { s += d; c += 1.0f; }
            d = v[j].w - tau; if (d > 0.0f) { s += d; c += 1.0f; }
        }
        #pragma unroll
        for (int o = 16; o; o >>= 1) {
            s += __shfl_xor_sync(0xffffffffu, s, o);
            c += __shfl_xor_sync(0xffffffffu, c, o);
        }
        float tn = tau + (s - 1.0f) / c;
        if (!(tn > tau)) break;   // converged (uniform across warp)
        tau = tn;
    }

    #pragma unroll
    for (int j = 0; j < 4; j++) {
        float4 y;
        y.x = fmaxf(v[j].x - tau, 0.0f);
        y.y = fmaxf(v[j].y - tau, 0.0f);
        y.z = fmaxf(v[j].z - tau, 0.0f);
        y.w = fmaxf(v[j].w - tau, 0.0f);
        rp[j * 32 + lane] = y;
    }
}

// ============================================================================
extern "C" void kernel_launch(void* const* d_in, const int* in_sizes, int n_in,
                              void* d_out, int out_size)
{
    (void)in_sizes; (void)n_in; (void)out_size;
    const float* priors = (const float*)d_in[0];
    const float* feat   = (const float*)d_in[1];
    const float* W      = (const float*)d_in[2];
    const float* gamma  = (const float*)d_in[3];
    const float* beta   = (const float*)d_in[4];
    float* out = (float*)d_out;

    cudaFuncSetAttribute(fused_gemm_gbn, cudaFuncAttributeMaxDynamicSharedMemorySize, SM_TOT);
    fused_gemm_gbn<<<N_B / VBS, 512, SM_TOT>>>(out, priors, feat, W, gamma, beta);
    sparsemax_k<<<N_B / 8, 256>>>(out);
}

// round 4
// speedup vs baseline: 1.1340x; 1.1340x over previous
#include <cuda_runtime.h>
#include <cuda_fp16.h>
#include <cstdint>

#define N_B    131072
#define D_IN   128
#define D_OUT  512
#define VBS    128
#define EPS_BN 1e-5f

// ---------------- SMEM layout (bytes) ----------------
// fp16 tiles: 128 rows x 128 cols fp16, 256B row stride, XOR-swizzled 16B chunks
#define SA      0           // A tile 32KB
#define SW      32768       // W tile 32KB
#define SSUM    65536       // 4 warpsM x 128 cols f32
#define SSQ     67584
#define SAB_A   69632       // 128 f32
#define SAB_B   70144
#define SM_TOT  70656

__device__ __forceinline__ uint32_t smem_u32(const void* p) {
    uint32_t a;
    asm("{ .reg .u64 t; cvta.to.shared.u64 t, %1; cvt.u32.u64 %0, t; }" : "=r"(a) : "l"(p));
    return a;
}
__device__ __forceinline__ void ldsm4(uint32_t* r, uint32_t addr) {
    asm volatile("ldmatrix.sync.aligned.m8n8.x4.shared.b16 {%0,%1,%2,%3}, [%4];"
                 : "=r"(r[0]), "=r"(r[1]), "=r"(r[2]), "=r"(r[3]) : "r"(addr));
}
__device__ __forceinline__ void mma16816(float* c, const uint32_t* a, const uint32_t* b) {
    asm volatile("mma.sync.aligned.m16n8k16.row.col.f32.f16.f16.f32 "
                 "{%0,%1,%2,%3}, {%4,%5,%6,%7}, {%8,%9}, {%0,%1,%2,%3};"
                 : "+f"(c[0]), "+f"(c[1]), "+f"(c[2]), "+f"(c[3])
                 : "r"(a[0]), "r"(a[1]), "r"(a[2]), "r"(a[3]), "r"(b[0]), "r"(b[1]));
}
__device__ __forceinline__ uint32_t pkh(float a, float b) {
    __half2 h = __floats2half2_rn(a, b);
    union { __half2 v; uint32_t u; } cv; cv.v = h;
    return cv.u;
}

// load a 128x128 f32 tile (row-major, stride 128) -> fp16, swizzled smem
__device__ __forceinline__ void load_tile_f16(const float* __restrict__ g,
                                              char* sm, int tid) {
    #pragma unroll
    for (int i = 0; i < 4; i++) {
        int idx = tid + i * 512;                 // 2048 chunk-slots of 16B
        int row = idx >> 4, ch = idx & 15;
        const float4* gp = reinterpret_cast<const float4*>(g + row * 128 + ch * 8);
        float4 u = gp[0], v = gp[1];
        uint4 h4 = make_uint4(pkh(u.x, u.y), pkh(u.z, u.w),
                              pkh(v.x, v.y), pkh(v.z, v.w));
        uint32_t off = (uint32_t)(row * 256 + ((ch ^ (row & 7)) << 4));
        *reinterpret_cast<uint4*>(sm + off) = h4;
    }
}

// ============================================================================
// Fully fused: fp16 mma.sync GEMM + GhostBN + priors + sparsemax (in-place
// via per-CTA L2 round-trip on the out buffer).
// grid = 1024 (one CTA per virtual batch of 128 rows), block = 512.
// ============================================================================
__global__ __launch_bounds__(512, 1) void fused_attentive(
    float* __restrict__ out, const float* __restrict__ priors,
    const float* __restrict__ feat, const float* __restrict__ W,
    const float* __restrict__ gamma, const float* __restrict__ beta)
{
    extern __shared__ char smem[];
    const uint32_t sb = smem_u32(smem);
    const int tid = threadIdx.x;
    const int w = tid >> 5, lane = tid & 31;
    const int mw = w & 3, nw = w >> 2;           // warp grid 4(M) x 4(N)
    const int m0 = blockIdx.x * VBS;

    float* ssum = reinterpret_cast<float*>(smem + SSUM);
    float* ssq  = reinterpret_cast<float*>(smem + SSQ);
    float* aarr = reinterpret_cast<float*>(smem + SAB_A);
    float* barr = reinterpret_cast<float*>(smem + SAB_B);

    // ---- A tile (feat 128x128) once ----
    load_tile_f16(feat + (size_t)m0 * D_IN, smem + SA, tid);

    // per-lane ldmatrix address components
    const int a_row = mw * 32 + (((lane >> 3) & 1) << 3) + (lane & 7);
    const int a_sel = lane >> 4;
    const int b_row = nw * 32 + ((lane >> 4) << 3) + (lane & 7);
    const int b_sel = (lane >> 3) & 1;
    const int a_m7 = a_row & 7, b_m7 = b_row & 7;

    #pragma unroll 1
    for (int chunk = 0; chunk < 4; chunk++) {
        // ---- W chunk (128 n-rows x 128 k) ----
        load_tile_f16(W + (size_t)chunk * 128 * D_IN, smem + SW, tid);
        __syncthreads();

        // ---- GEMM: warp tile 32(M) x 32(N) ----
        float acc[2][4][4];
        #pragma unroll
        for (int mt = 0; mt < 2; mt++)
            #pragma unroll
            for (int nt = 0; nt < 4; nt++)
                #pragma unroll
                for (int q = 0; q < 4; q++) acc[mt][nt][q] = 0.0f;

        #pragma unroll
        for (int s = 0; s < 8; s++) {
            uint32_t aF[2][4], bF[2][4];
            #pragma unroll
            for (int mt = 0; mt < 2; mt++) {
                uint32_t off = (uint32_t)((a_row + mt * 16) * 256 +
                               (((2 * s + a_sel) ^ a_m7) << 4));
                ldsm4(aF[mt], sb + SA + off);
            }
            #pragma unroll
            for (int np = 0; np < 2; np++) {
                uint32_t off = (uint32_t)((b_row + np * 16) * 256 +
                               (((2 * s + b_sel) ^ b_m7) << 4));
                ldsm4(bF[np], sb + SW + off);
            }
            #pragma unroll
            for (int mt = 0; mt < 2; mt++)
                #pragma unroll
                for (int nt = 0; nt < 4; nt++)
                    mma16816(acc[mt][nt], aF[mt], &bF[nt >> 1][(nt & 1) * 2]);
        }

        // ---- column stats over this warp's 32 rows ----
        #pragma unroll
        for (int nt = 0; nt < 4; nt++) {
            float s0 = 0.f, s1 = 0.f, q0 = 0.f, q1 = 0.f;
            #pragma unroll
            for (int mt = 0; mt < 2; mt++) {
                float c0 = acc[mt][nt][0], c1 = acc[mt][nt][1];
                float c2 = acc[mt][nt][2], c3 = acc[mt][nt][3];
                s0 += c0 + c2;  s1 += c1 + c3;
                q0 += c0 * c0 + c2 * c2;  q1 += c1 * c1 + c3 * c3;
            }
            #pragma unroll
            for (int o = 4; o < 32; o <<= 1) {
                s0 += __shfl_xor_sync(0xffffffffu, s0, o);
                s1 += __shfl_xor_sync(0xffffffffu, s1, o);
                q0 += __shfl_xor_sync(0xffffffffu, q0, o);
                q1 += __shfl_xor_sync(0xffffffffu, q1, o);
            }
            if (lane < 4) {
                int col = nw * 32 + nt * 8 + 2 * lane;
                ssum[mw * 128 + col]     = s0;  ssum[mw * 128 + col + 1] = s1;
                ssq [mw * 128 + col]     = q0;  ssq [mw * 128 + col + 1] = q1;
            }
        }
        __syncthreads();

        // ---- fold BN into per-col affine (deterministic combine) ----
        if (tid < 128) {
            int c = tid;
            float s = ssum[c] + ssum[128 + c] + ssum[256 + c] + ssum[384 + c];
            float q = ssq[c]  + ssq[128 + c]  + ssq[256 + c]  + ssq[384 + c];
            float mean = s * (1.0f / VBS);
            float var  = q * (1.0f / VBS) - mean * mean;
            float av = gamma[chunk * 128 + c] * rsqrtf(var + EPS_BN);
            aarr[c] = av;
            barr[c] = beta[chunk * 128 + c] - mean * av;
        }
        __syncthreads();

        // ---- apply affine + priors, stage y to out (L2-resident) ----
        #pragma unroll
        for (int nt = 0; nt < 4; nt++) {
            int col = nw * 32 + nt * 8 + 2 * (lane & 3);
            int gcol = chunk * 128 + col;
            float a0 = aarr[col],     b0 = barr[col];
            float a1 = aarr[col + 1], b1 = barr[col + 1];
            #pragma unroll
            for (int mt = 0; mt < 2; mt++) {
                int r0 = m0 + mw * 32 + mt * 16 + (lane >> 2);
                int r1 = r0 + 8;
                float2 p0 = *reinterpret_cast<const float2*>(priors + (size_t)r0 * D_OUT + gcol);
                float2 p1 = *reinterpret_cast<const float2*>(priors + (size_t)r1 * D_OUT + gcol);
                float2 y0, y1;
                y0.x = fmaf(acc[mt][nt][0], a0, b0) * p0.x;
                y0.y = fmaf(acc[mt][nt][1], a1, b1) * p0.y;
                y1.x = fmaf(acc[mt][nt][2], a0, b0) * p1.x;
                y1.y = fmaf(acc[mt][nt][3], a1, b1) * p1.y;
                *reinterpret_cast<float2*>(out + (size_t)r0 * D_OUT + gcol) = y0;
                *reinterpret_cast<float2*>(out + (size_t)r1 * D_OUT + gcol) = y1;
            }
        }
        __syncthreads();   // y stores visible CTA-wide; W tile safe to overwrite
    }

    // ======================= fused sparsemax tail ===========================
    // Each warp: 8 complete rows of this CTA; y re-read is an L2 hit (just
    // written by this CTA). Monotone Newton on f(t)=sum relu(y-t)-1 from
    // t0=max-1: exact fixed point of the piecewise-linear equation, no sort.
    #pragma unroll 1
    for (int r = 0; r < 8; r++) {
        const int row = m0 + w * 8 + r;
        float4* rp = reinterpret_cast<float4*>(out + (size_t)row * D_OUT);

        float4 v[4];
        #pragma unroll
        for (int j = 0; j < 4; j++) v[j] = rp[j * 32 + lane];

        float m = v[0].x;
        #pragma unroll
        for (int j = 0; j < 4; j++) {
            m = fmaxf(m, v[j].x); m = fmaxf(m, v[j].y);
            m = fmaxf(m, v[j].z); m = fmaxf(m, v[j].w);
        }
        #pragma unroll
        for (int o = 16; o; o >>= 1) m = fmaxf(m, __shfl_xor_sync(0xffffffffu, m, o));

        float tau = m - 1.0f;
        #pragma unroll 1
        for (int it = 0; it < 64; it++) {
            float s = 0.0f, c = 0.0f;
            #pragma unroll
            for (int j = 0; j < 4; j++) {
                float d;
                d = v[j].x - tau; if (d > 0.0f) { s += d; c += 1.0f; }
                d = v[j].y - tau; if (d > 0.0f) { s += d; c += 1.0f; }
                d = v[j].z - tau; if (d > 0.0f) { s += d; c += 1.0f; }
                d = v[j].w - tau; if (d > 0.0f) { s += d; c += 1.0f; }
            }
            #pragma unroll
            for (int o = 16; o; o >>= 1) {
                s += __shfl_xor_sync(0xffffffffu, s, o);
                c += __shfl_xor_sync(0xffffffffu, c, o);
            }
            float tn = tau + (s - 1.0f) / c;
            if (!(tn > tau)) break;   // converged (uniform across warp)
            tau = tn;
        }

        #pragma unroll
        for (int j = 0; j < 4; j++) {
            float4 y;
            y.x = fmaxf(v[j].x - tau, 0.0f);
            y.y = fmaxf(v[j].y - tau, 0.0f);
            y.z = fmaxf(v[j].z - tau, 0.0f);
            y.w = fmaxf(v[j].w - tau, 0.0f);
            rp[j * 32 + lane] = y;
        }
    }
}

// ============================================================================
extern "C" void kernel_launch(void* const* d_in, const int* in_sizes, int n_in,
                              void* d_out, int out_size)
{
    (void)in_sizes; (void)n_in; (void)out_size;
    const float* priors = (const float*)d_in[0];
    const float* feat   = (const float*)d_in[1];
    const float* W      = (const float*)d_in[2];
    const float* gamma  = (const float*)d_in[3];
    const float* beta   = (const float*)d_in[4];
    float* out = (float*)d_out;

    cudaFuncSetAttribute(fused_attentive, cudaFuncAttributeMaxDynamicSharedMemorySize, SM_TOT);
    fused_attentive<<<N_B / VBS, 512, SM_TOT>>>(out, priors, feat, W, gamma, beta);
}

// round 9
// speedup vs baseline: 1.4452x; 1.2745x over previous
#include <cuda_runtime.h>
#include <cuda_fp16.h>
#include <cstdint>

#define N_B    131072
#define D_IN   128
#define D_OUT  512
#define VBS    128
#define EPS_BN 1e-5f

// ---------------- SMEM layout (bytes) ----------------
#define SA      0           // A tile 32KB (128x128 fp16, 256B row stride, swizzled)
#define SW0     32768       // W tile buffer 0, 32KB
#define SW1     65536       // W tile buffer 1, 32KB
#define SSUM    98304       // 4 (mw) x 512 cols f32 partial sums
#define SSQ     106496      // 4 x 512 f32 partial sumsq
#define SAB_A   114688      // 512 f32 affine scale
#define SAB_B   116736      // 512 f32 affine shift
#define SM_TOT  118784

// W pre-converted to fp16, swizzled, chunk-tiled: 4 chunks x 32KB
__device__ __align__(16) unsigned char gWh[131072];

__device__ __forceinline__ uint32_t smem_u32(const void* p) {
    uint32_t a;
    asm("{ .reg .u64 t; cvta.to.shared.u64 t, %1; cvt.u32.u64 %0, t; }" : "=r"(a) : "l"(p));
    return a;
}
__device__ __forceinline__ void ldsm4(uint32_t* r, uint32_t addr) {
    asm volatile("ldmatrix.sync.aligned.m8n8.x4.shared.b16 {%0,%1,%2,%3}, [%4];"
                 : "=r"(r[0]), "=r"(r[1]), "=r"(r[2]), "=r"(r[3]) : "r"(addr));
}
__device__ __forceinline__ void mma16816(float* c, const uint32_t* a, const uint32_t* b) {
    asm volatile("mma.sync.aligned.m16n8k16.row.col.f32.f16.f16.f32 "
                 "{%0,%1,%2,%3}, {%4,%5,%6,%7}, {%8,%9}, {%0,%1,%2,%3};"
                 : "+f"(c[0]), "+f"(c[1]), "+f"(c[2]), "+f"(c[3])
                 : "r"(a[0]), "r"(a[1]), "r"(a[2]), "r"(a[3]), "r"(b[0]), "r"(b[1]));
}
__device__ __forceinline__ uint32_t pkh(float a, float b) {
    __half2 h = __floats2half2_rn(a, b);
    union { __half2 v; uint32_t u; } cv; cv.v = h;
    return cv.u;
}
__device__ __forceinline__ void cp16(uint32_t saddr, const void* g) {
    asm volatile("cp.async.cg.shared.global [%0], [%1], 16;" :: "r"(saddr), "l"(g) : "memory");
}
__device__ __forceinline__ void cp_commit() {
    asm volatile("cp.async.commit_group;" ::: "memory");
}

// load a 128x128 f32 tile (row-major, stride 128) -> fp16, swizzled smem
__device__ __forceinline__ void load_tile_f16(const float* __restrict__ g,
                                              char* sm, int tid) {
    #pragma unroll
    for (int i = 0; i < 4; i++) {
        int idx = tid + i * 512;                 // 2048 16B chunk-slots
        int row = idx >> 4, ch = idx & 15;
        const float4* gp = reinterpret_cast<const float4*>(g + row * 128 + ch * 8);
        float4 u = gp[0], v = gp[1];
        uint4 h4 = make_uint4(pkh(u.x, u.y), pkh(u.z, u.w),
                              pkh(v.x, v.y), pkh(v.z, v.w));
        uint32_t off = (uint32_t)(row * 256 + ((ch ^ (row & 7)) << 4));
        *reinterpret_cast<uint4*>(sm + off) = h4;
    }
}

// ============================================================================
// Prep: W [512,128] f32 -> fp16, swizzled, chunk-tiled in gWh (runs once per
// launch, ~128KB of work, deterministic).
// ============================================================================
__global__ __launch_bounds__(256) void prep_w(const float* __restrict__ W) {
    int idx = blockIdx.x * 256 + threadIdx.x;    // 0..8191 (16B chunks)
    int c = idx >> 11, j = idx & 2047;
    int row = j >> 4, ch = j & 15;
    const float4* gp = reinterpret_cast<const float4*>(W + ((size_t)(c * 128 + row) * 128 + ch * 8));
    float4 u = gp[0], v = gp[1];
    uint4 h4 = make_uint4(pkh(u.x, u.y), pkh(u.z, u.w),
                          pkh(v.x, v.y), pkh(v.z, v.w));
    *reinterpret_cast<uint4*>(gWh + c * 32768 + row * 256 + ((ch ^ (row & 7)) << 4)) = h4;
}

// ============================================================================
// Fused: fp16 mma GEMM (raw x -> out, L2-resident) + deferred GhostBN fold +
// sparsemax tail applying (x*a+b)*prior in-register.
// grid = 1024 (one CTA per virtual batch of 128 rows), block = 512.
// ============================================================================
__global__ __launch_bounds__(512, 1) void fused_attentive(
    float* __restrict__ out, const float* __restrict__ priors,
    const float* __restrict__ feat,
    const float* __restrict__ gamma, const float* __restrict__ beta)
{
    extern __shared__ char smem[];
    const uint32_t sb = smem_u32(smem);
    const int tid = threadIdx.x;
    const int w = tid >> 5, lane = tid & 31;
    const int mw = w & 3, nw = w >> 2;           // warp grid 4(M) x 4(N)
    const int m0 = blockIdx.x * VBS;

    float* ssum = reinterpret_cast<float*>(smem + SSUM);
    float* ssq  = reinterpret_cast<float*>(smem + SSQ);
    float* aarr = reinterpret_cast<float*>(smem + SAB_A);
    float* barr = reinterpret_cast<float*>(smem + SAB_B);

    // ---- prefetch W chunks 0,1 via cp.async (pre-swizzled fp16: linear copy) ----
    #pragma unroll
    for (int i = 0; i < 4; i++) {
        int idx = tid + i * 512;
        cp16(sb + SW0 + idx * 16, gWh + idx * 16);
    }
    cp_commit();
    #pragma unroll
    for (int i = 0; i < 4; i++) {
        int idx = tid + i * 512;
        cp16(sb + SW1 + idx * 16, gWh + 32768 + idx * 16);
    }
    cp_commit();

    // ---- A tile (feat 128x128) — conversion overlaps W cp.async ----
    load_tile_f16(feat + (size_t)m0 * D_IN, smem + SA, tid);

    // per-lane ldmatrix address components
    const int a_row = mw * 32 + (((lane >> 3) & 1) << 3) + (lane & 7);
    const int a_sel = lane >> 4;
    const int b_row = nw * 32 + ((lane >> 4) << 3) + (lane & 7);
    const int b_sel = (lane >> 3) & 1;
    const int a_m7 = a_row & 7, b_m7 = b_row & 7;

    #pragma unroll 1
    for (int chunk = 0; chunk < 4; chunk++) {
        // wait for this chunk's W buffer, then make it (and A) block-visible
        if (chunk < 3) asm volatile("cp.async.wait_group 1;" ::: "memory");
        else           asm volatile("cp.async.wait_group 0;" ::: "memory");
        __syncthreads();
        const uint32_t swb = (chunk & 1) ? (sb + SW1) : (sb + SW0);

        // ---- GEMM: warp tile 32(M) x 32(N) ----
        float acc[2][4][4];
        #pragma unroll
        for (int mt = 0; mt < 2; mt++)
            #pragma unroll
            for (int nt = 0; nt < 4; nt++)
                #pragma unroll
                for (int q = 0; q < 4; q++) acc[mt][nt][q] = 0.0f;

        #pragma unroll
        for (int s = 0; s < 8; s++) {
            uint32_t aF[2][4], bF[2][4];
            #pragma unroll
            for (int mt = 0; mt < 2; mt++) {
                uint32_t off = (uint32_t)((a_row + mt * 16) * 256 +
                               (((2 * s + a_sel) ^ a_m7) << 4));
                ldsm4(aF[mt], sb + SA + off);
            }
            #pragma unroll
            for (int np = 0; np < 2; np++) {
                uint32_t off = (uint32_t)((b_row + np * 16) * 256 +
                               (((2 * s + b_sel) ^ b_m7) << 4));
                ldsm4(bF[np], swb + off);
            }
            #pragma unroll
            for (int mt = 0; mt < 2; mt++)
                #pragma unroll
                for (int nt = 0; nt < 4; nt++)
                    mma16816(acc[mt][nt], aF[mt], &bF[nt >> 1][(nt & 1) * 2]);
        }

        // ---- store raw x to out (L2-resident round trip) ----
        #pragma unroll
        for (int nt = 0; nt < 4; nt++) {
            int gcol = chunk * 128 + nw * 32 + nt * 8 + 2 * (lane & 3);
            #pragma unroll
            for (int mt = 0; mt < 2; mt++) {
                int r0 = m0 + mw * 32 + mt * 16 + (lane >> 2);
                *reinterpret_cast<float2*>(out + (size_t)r0 * D_OUT + gcol) =
                    make_float2(acc[mt][nt][0], acc[mt][nt][1]);
                *reinterpret_cast<float2*>(out + (size_t)(r0 + 8) * D_OUT + gcol) =
                    make_float2(acc[mt][nt][2], acc[mt][nt][3]);
            }
        }

        // ---- column stats (race-free slots: (mw, global col) unique; no sync) ----
        #pragma unroll
        for (int nt = 0; nt < 4; nt++) {
            float s0 = 0.f, s1 = 0.f, q0 = 0.f, q1 = 0.f;
            #pragma unroll
            for (int mt = 0; mt < 2; mt++) {
                float c0 = acc[mt][nt][0], c1 = acc[mt][nt][1];
                float c2 = acc[mt][nt][2], c3 = acc[mt][nt][3];
                s0 += c0 + c2;  s1 += c1 + c3;
                q0 += c0 * c0 + c2 * c2;  q1 += c1 * c1 + c3 * c3;
            }
            #pragma unroll
            for (int o = 4; o < 32; o <<= 1) {
                s0 += __shfl_xor_sync(0xffffffffu, s0, o);
                s1 += __shfl_xor_sync(0xffffffffu, s1, o);
                q0 += __shfl_xor_sync(0xffffffffu, q0, o);
                q1 += __shfl_xor_sync(0xffffffffu, q1, o);
            }
            if (lane < 4) {
                int gcol = chunk * 128 + nw * 32 + nt * 8 + 2 * lane;
                ssum[mw * 512 + gcol]     = s0;  ssum[mw * 512 + gcol + 1] = s1;
                ssq [mw * 512 + gcol]     = q0;  ssq [mw * 512 + gcol + 1] = q1;
            }
        }
        __syncthreads();   // MMA reads of swb done -> safe to prefetch into it

        if (chunk + 2 < 4) {
            const unsigned char* src = gWh + (chunk + 2) * 32768;
            #pragma unroll
            for (int i = 0; i < 4; i++) {
                int idx = tid + i * 512;
                cp16(swb + idx * 16, src + idx * 16);
            }
            cp_commit();
        }
    }

    // ---- fold BN into per-col affine (once, deterministic combine) ----
    {
        int c = tid;                               // 512 threads = 512 cols
        float s = ssum[c] + ssum[512 + c] + ssum[1024 + c] + ssum[1536 + c];
        float q = ssq[c]  + ssq[512 + c]  + ssq[1024 + c]  + ssq[1536 + c];
        float mean = s * (1.0f / VBS);
        float var  = q * (1.0f / VBS) - mean * mean;
        float av = gamma[c] * rsqrtf(var + EPS_BN);
        aarr[c] = av;
        barr[c] = beta[c] - mean * av;
    }
    __syncthreads();

    // ======================= fused sparsemax tail ===========================
    // Warp-per-row (8 rows each). x re-read is an L2 hit (written above by
    // this CTA); y=(x*a+b)*prior formed in-register; monotone Newton on
    // f(t)=sum relu(y-t)-1 from t0=max-1 (exact piecewise-linear fixed point).
    #pragma unroll 1
    for (int r = 0; r < 8; r++) {
        const int row = m0 + w * 8 + r;
        float4* rp = reinterpret_cast<float4*>(out + (size_t)row * D_OUT);
        const float4* pp = reinterpret_cast<const float4*>(priors + (size_t)row * D_OUT);

        float4 v[4];
        #pragma unroll
        for (int j = 0; j < 4; j++) {
            float4 x = rp[j * 32 + lane];
            float4 p = pp[j * 32 + lane];
            float4 a4 = *reinterpret_cast<const float4*>(aarr + j * 128 + lane * 4);
            float4 b4 = *reinterpret_cast<const float4*>(barr + j * 128 + lane * 4);
            v[j].x = fmaf(x.x, a4.x, b4.x) * p.x;
            v[j].y = fmaf(x.y, a4.y, b4.y) * p.y;
            v[j].z = fmaf(x.z, a4.z, b4.z) * p.z;
            v[j].w = fmaf(x.w, a4.w, b4.w) * p.w;
        }

        float m = v[0].x;
        #pragma unroll
        for (int j = 0; j < 4; j++) {
            m = fmaxf(m, v[j].x); m = fmaxf(m, v[j].y);
            m = fmaxf(m, v[j].z); m = fmaxf(m, v[j].w);
        }
        #pragma unroll
        for (int o = 16; o; o >>= 1) m = fmaxf(m, __shfl_xor_sync(0xffffffffu, m, o));

        float tau = m - 1.0f;
        #pragma unroll 1
        for (int it = 0; it < 64; it++) {
            float s = 0.0f, c = 0.0f;
            #pragma unroll
            for (int j = 0; j < 4; j++) {
                float d;
                d = v[j].x - tau; if (d > 0.0f) { s += d; c += 1.0f; }
                d = v[j].y - tau; if (d > 0.0f) { s += d; c += 1.0f; }
                d = v[j].z - tau; if (d > 0.0f) { s += d; c += 1.0f; }
                d = v[j].w - tau; if (d > 0.0f) { s += d; c += 1.0f; }
            }
            #pragma unroll
            for (int o = 16; o; o >>= 1) {
                s += __shfl_xor_sync(0xffffffffu, s, o);
                c += __shfl_xor_sync(0xffffffffu, c, o);
            }
            float tn = tau + (s - 1.0f) / c;
            if (!(tn > tau)) break;   // converged (uniform across warp)
            tau = tn;
        }

        #pragma unroll
        for (int j = 0; j < 4; j++) {
            float4 y;
            y.x = fmaxf(v[j].x - tau, 0.0f);
            y.y = fmaxf(v[j].y - tau, 0.0f);
            y.z = fmaxf(v[j].z - tau, 0.0f);
            y.w = fmaxf(v[j].w - tau, 0.0f);
            rp[j * 32 + lane] = y;
        }
    }
}

// ============================================================================
extern "C" void kernel_launch(void* const* d_in, const int* in_sizes, int n_in,
                              void* d_out, int out_size)
{
    (void)in_sizes; (void)n_in; (void)out_size;
    const float* priors = (const float*)d_in[0];
    const float* feat   = (const float*)d_in[1];
    const float* W      = (const float*)d_in[2];
    const float* gamma  = (const float*)d_in[3];
    const float* beta   = (const float*)d_in[4];
    float* out = (float*)d_out;

    prep_w<<<32, 256>>>(W);
    cudaFuncSetAttribute(fused_attentive, cudaFuncAttributeMaxDynamicSharedMemorySize, SM_TOT);
    fused_attentive<<<N_B / VBS, 512, SM_TOT>>>(out, priors, feat, gamma, beta);
}